// round 12
// baseline (speedup 1.0000x reference)
#include <cuda_runtime.h>
#include <math.h>

// Problem constants
#define Bc 16
#define Ac 3
#define Cc 80
#define Hc 76
#define Wc 76
#define Tc 50
#define Sc (Hc * Wc)            // 5776 (divisible by 4)
#define NCELL (Bc * Ac * Sc)    // 277248
#define NCH 85
#define NT (Bc * Tc)            // 800 targets
#define NSUPW (NCELL / 32)      // 8664 suppression words (exact)

#define TPB 256
#define NWARPS (TPB / 32)
#define NQ (NCELL / 4)          // 69312 float4 cells
#define NB ((NQ + TPB - 1) / TPB)   // 271 blocks -> 2168 warps >= 800 entries

#define BTPB 800                // build threads: one per target

#define KINV 0xFFFFFFFFu

// ---------------------------------------------------------------------------
// Scratch (device globals, no allocation)
// ---------------------------------------------------------------------------
__device__ unsigned g_sup[NSUPW];     // suppression bitmask (noobj=0 cells)
__device__ int      g_nsup;           // popcount of suppression bits
__device__ unsigned g_ekey[NT];       // (cell<<7)|cls, or KINV
__device__ unsigned g_eflag[NT];      // bit0 = winner, bit1 = first (cell,cls)
__device__ float4   g_evals[NT];      // tx,ty,tw,th
__device__ float    g_part[NB];       // per-block noobj-bce partials
__device__ float    g_epart[NT * 8];  // per-entry: x,y,w,h,conf,cls,mask,pad
__device__ unsigned g_done = 0;

// softplus via MUFU intrinsics. bce(sigmoid(x), t) == softplus(x) - t*x
// (reference clip(-100) unreachable for finite normal logits).
__device__ __forceinline__ float softplusf(float x) {
    return fmaxf(x, 0.0f) + __logf(1.0f + __expf(-fabsf(x)));
}

// ---------------------------------------------------------------------------
// Kernel 1: build. One block, 800 threads — one thread per target.
// Adds a popcount pass over the suppression bitmask so main never counts.
// ---------------------------------------------------------------------------
__global__ void __launch_bounds__(BTPB) yolo_build_kernel(const float* __restrict__ tgt) {
    __shared__ float    s[NT * 5];        // 16 KB staged targets
    __shared__ unsigned skey[NT];
    __shared__ float4   svals[NT];
    __shared__ int      ssup;

    int e = threadIdx.x;                  // target index, 0..799

    // phase A: zero suppression bits + stage targets
    if (e == 0) ssup = 0;
    for (int i = e; i < NSUPW; i += BTPB) g_sup[i] = 0u;
    for (int i = e; i < NT * 5; i += BTPB) s[i] = tgt[i];
    __syncthreads();

    // phase B: per-target compute (fully parallel; RED.OR idempotent)
    {
        // SA = ANCHORS / (608/76) = ANCHORS / 8 (exact in binary)
        const float aw[3] = {1.25f, 2.0f, 4.125f};
        const float ah[3] = {1.625f, 3.75f, 2.875f};

        int b = e / Tc;
        const float* r = s + e * 5;
        float c0 = r[0], c1 = r[1], c2 = r[2], c3 = r[3], c4 = r[4];
        unsigned key = KINV;
        float4 tv = make_float4(0.f, 0.f, 0.f, 0.f);

        if ((c0 + c1 + c2 + c3 + c4) != 0.0f) {      // valid
            int   cls = (int)c0;
            float gx = c1 * (float)Wc;
            float gy = c2 * (float)Hc;
            float gw = c3 * (float)Wc;
            float gh = c4 * (float)Hc;
            int gi = (int)gx;
            int gj = (int)gy;

            float a1 = (gw + 1.0f) * (gh + 1.0f);
            float iou[3];
            int best = 0;
            #pragma unroll
            for (int a = 0; a < 3; a++) {
                float iw = fmaxf(fminf(gw, aw[a]) + 1.0f, 0.0f);
                float ih = fmaxf(fminf(gh, ah[a]) + 1.0f, 0.0f);
                float inter = iw * ih;
                float a2 = (aw[a] + 1.0f) * (ah[a] + 1.0f);
                iou[a] = inter / (a1 + a2 - inter + 1e-16f);
                if (iou[a] > iou[best]) best = a;
            }

            #pragma unroll
            for (int a = 0; a < 3; a++) {
                if (iou[a] > 0.5f) {
                    long long idx = (((long long)(b * Ac + a) * Hc + gj) * Wc + gi);
                    if (idx >= 0 && idx < NCELL) {
                        int ii = (int)idx;
                        atomicOr(&g_sup[ii >> 5], 1u << (ii & 31));
                    }
                }
            }

            if (gj < Hc && gi < Wc) {
                long long cell = (((long long)(b * Ac + best) * Hc + gj) * Wc + gi);
                if (cell >= 0 && cell < NCELL && cls >= 0 && cls < Cc) {
                    key = ((unsigned)cell << 7) | (unsigned)cls;
                    tv.x = gx - (float)gi;
                    tv.y = gy - (float)gj;
                    tv.z = logf(gw / aw[best] + 1e-16f);
                    tv.w = logf(gh / ah[best] + 1e-16f);
                }
            }
        }
        skey[e] = key;
        svals[e] = tv;
    }
    __syncthreads();

    // phase C: winner/first flags (parallel scan) + suppression popcount
    {
        unsigned k = skey[e];
        unsigned fl = 0u;
        if (k != KINV) {
            int base = (e / Tc) * Tc;
            unsigned mycell = k >> 7;
            bool win = true, first = true;
            #pragma unroll 5
            for (int t2 = 0; t2 < Tc; t2++) {
                int e2 = base + t2;
                unsigned k2 = skey[e2];
                bool samecell = (k2 != KINV) && ((k2 >> 7) == mycell);
                if (e2 > e && samecell) win = false;
                if (e2 < e && k2 == k)  first = false;
            }
            fl = (win ? 1u : 0u) | (first ? 2u : 0u);
        }
        g_ekey[e] = k;
        g_eflag[e] = fl;
        g_evals[e] = svals[e];

        int pc = 0;
        for (int i = e; i < NSUPW; i += BTPB) pc += __popc(g_sup[i]);
        // integer add: associative -> deterministic
        if (pc) atomicAdd(&ssup, pc);
    }
    __syncthreads();
    if (e == 0) g_nsup = ssup;
}

// ---------------------------------------------------------------------------
// Kernel 2: main.
//  - Per-thread: 4 cells (float4 conf load) -> ONE reduced slot (noobj bce).
//  - Per-warp: one masked entry; class loop lane-split, warp shuffle reduce,
//    lane 0 writes a compact 8-float record to g_epart (fixed mapping =>
//    deterministic). No 9-slot tree anywhere.
// ---------------------------------------------------------------------------
__global__ void __launch_bounds__(TPB) yolo_main_kernel(
        const float* __restrict__ inp, float* __restrict__ out, int out_size) {
    int i4 = blockIdx.x * TPB + threadIdx.x;
    int lane = threadIdx.x & 31;
    int wid  = threadIdx.x >> 5;

    // --- per-cell noobj bce, 4 cells per thread ---
    float v0 = 0.0f;
    if (i4 < NQ) {
        int cell0 = i4 * 4;
        int g  = cell0 / Sc;
        int hw = cell0 - g * Sc;
        const float4 c4 = *reinterpret_cast<const float4*>(
            inp + (size_t)g * NCH * Sc + 4 * Sc + hw);
        unsigned w  = g_sup[cell0 >> 5];
        unsigned sh = (unsigned)cell0 & 31u;
        float cj[4] = {c4.x, c4.y, c4.z, c4.w};
        #pragma unroll
        for (int j = 0; j < 4; j++)
            if (!((w >> (sh + j)) & 1u))
                v0 += softplusf(cj[j]);           // bce(conf, 0)
    }

    // --- per-entry masked terms: one warp per entry ---
    int we = blockIdx.x * NWARPS + wid;
    if (we < NT) {
        unsigned k = g_ekey[we];                  // warp-uniform
        float ecls = 0.0f;
        float ex = 0.f, ey = 0.f, ew = 0.f, eh = 0.f, ec = 0.f, em = 0.f;
        if (k != KINV) {
            unsigned fl = g_eflag[we];
            int cell = (int)(k >> 7);
            int cls  = (int)(k & 127u);
            int g  = cell / Sc;
            int hw = cell - g * Sc;
            const float* base = inp + (size_t)g * NCH * Sc + hw;

            if (fl & 1u) {                        // winner: class softplus sum
                #pragma unroll
                for (int c = lane; c < Cc; c += 32)
                    ecls += softplusf(base[(5 + c) * Sc]);
            }
            if ((fl & 2u) && lane == 1)           // distinct (cell,cls)
                ecls -= base[(5 + cls) * Sc];

            // warp reduce class term (deterministic fixed order)
            #pragma unroll
            for (int off = 16; off > 0; off >>= 1)
                ecls += __shfl_down_sync(0xffffffffu, ecls, off);

            if ((fl & 1u) && lane == 0) {
                float4 tv = g_evals[we];
                float x0 = base[0];
                float x1 = base[Sc];
                float x2 = base[2 * Sc];
                float x3 = base[3 * Sc];
                float x4 = base[4 * Sc];
                ex = softplusf(x0) - tv.x * x0;
                ey = softplusf(x1) - tv.y * x1;
                float dw = x2 - tv.z; ew = dw * dw;
                float dh = x3 - tv.w; eh = dh * dh;
                ec = softplusf(-x4);              // bce(conf, 1)
                em = 1.0f;
            }
        } else {
            #pragma unroll
            for (int off = 16; off > 0; off >>= 1)
                ecls += __shfl_down_sync(0xffffffffu, ecls, off);
        }
        if (lane == 0) {
            float* ep = g_epart + we * 8;
            ep[0] = ex; ep[1] = ey; ep[2] = ew; ep[3] = eh;
            ep[4] = ec; ep[5] = ecls; ep[6] = em; ep[7] = 0.0f;
        }
    }

    // --- single-slot deterministic block reduce ---
    #pragma unroll
    for (int off = 16; off > 0; off >>= 1)
        v0 += __shfl_down_sync(0xffffffffu, v0, off);

    __shared__ float swarp[NWARPS];
    if (lane == 0) swarp[wid] = v0;
    __syncthreads();
    if (threadIdx.x == 0) {
        float b = 0.0f;
        #pragma unroll
        for (int w2 = 0; w2 < NWARPS; w2++) b += swarp[w2];
        g_part[blockIdx.x] = b;
    }

    // --- last-block ticket ---
    __shared__ int is_last;
    __threadfence();
    if (threadIdx.x == 0) {
        unsigned t = atomicAdd(&g_done, 1u);
        is_last = (t == NB - 1);
        if (is_last) g_done = 0;              // reset for next replay
    }
    __syncthreads();

    if (is_last) {
        // noobj bce total (fixed order over blocks)
        float a0 = 0.0f;
        for (int j = threadIdx.x; j < NB; j += TPB)
            a0 += __ldcg(&g_part[j]);

        // entry totals (fixed order over entries)
        float a[7];
        #pragma unroll
        for (int k = 0; k < 7; k++) a[k] = 0.0f;
        for (int e = threadIdx.x; e < NT; e += TPB) {
            const float* ep = g_epart + e * 8;
            #pragma unroll
            for (int k = 0; k < 7; k++) a[k] += __ldcg(&ep[k]);
        }

        #pragma unroll
        for (int off = 16; off > 0; off >>= 1) {
            a0 += __shfl_down_sync(0xffffffffu, a0, off);
            #pragma unroll
            for (int k = 0; k < 7; k++)
                a[k] += __shfl_down_sync(0xffffffffu, a[k], off);
        }
        __shared__ float sfin[NWARPS][8];
        if (lane == 0) {
            sfin[wid][0] = a0;
            #pragma unroll
            for (int k = 0; k < 7; k++) sfin[wid][k + 1] = a[k];
        }
        __syncthreads();

        if (threadIdx.x == 0) {
            float tot[8];
            #pragma unroll
            for (int k = 0; k < 8; k++) {
                float t = 0.0f;
                #pragma unroll
                for (int w2 = 0; w2 < NWARPS; w2++) t += sfin[w2][k];
                tot[k] = t;
            }
            // tot: 0=noobj_bce 1=x 2=y 3=w 4=h 5=conf_obj 6=cls 7=n_mask
            const float N = (float)NCELL;
            float n_m  = tot[7];
            float n_nm = (float)(NCELL - g_nsup);
            float loss_x = tot[1] / N / n_m;
            float loss_y = tot[2] / N / n_m;
            float loss_w = tot[3] / N / n_m;
            float loss_h = tot[4] / N / n_m;
            float loss_conf = tot[5] / N / n_m + 0.5f * tot[0] / N / n_nm;
            float loss_cls  = tot[6] / (n_m * (float)Cc) / n_m;
            float loss = 2.5f * (loss_x + loss_y) + 2.5f * (loss_w + loss_h)
                       + loss_conf + loss_cls;
            float res[7] = {loss, loss_x, loss_y, loss_w, loss_h,
                            loss_conf, loss_cls};
            for (int k = 0; k < 7 && k < out_size; k++) out[k] = res[k];
        }
    }
}

// ---------------------------------------------------------------------------
extern "C" void kernel_launch(void* const* d_in, const int* in_sizes, int n_in,
                              void* d_out, int out_size) {
    const float* inp = (const float*)d_in[0];
    const float* tgt = (const float*)d_in[1];
    if (n_in >= 2 && in_sizes[0] < in_sizes[1]) {   // defensive
        const float* tmp = inp; inp = tgt; tgt = tmp;
    }

    yolo_build_kernel<<<1, BTPB>>>(tgt);
    yolo_main_kernel<<<NB, TPB>>>(inp, (float*)d_out, out_size);
}